// round 2
// baseline (speedup 1.0000x reference)
#include <cuda_runtime.h>
#include <cstddef>

// ---------------------------------------------------------------------------
// RibonanzaNet pairwise mixer (outgoing triangle multiplication)
// B=2, L=512, C=64, fp32.
//
// Stage 1 (k_proj):  x = LN(in); left/right/og projections fused; outputs
//                    written TRANSPOSED to [b,c,i,k] so stage 2 is a clean
//                    batched K-major NT SGEMM.
// Stage 2 (k_tri):   tri[b,c,i,j] = sum_k left[b,c,i,k] * right[b,c,j,k]
//                    128 batches of 512x512x512 NT SGEMM.
// Stage 3 (k_out):   y = (LN(tri) * og) @ W_out + b_out + residual.
//
// All three hot loops use packed fma.rn.f32x2 (Blackwell FFMA2): 2 fp32 FMAs
// per issue slot; ptxas never auto-fuses this from C++.
// ---------------------------------------------------------------------------

#define L_DIM 512
#define C_DIM 64
#define SLICE (L_DIM * L_DIM)      // 262144
#define NBATCH (2 * C_DIM)         // 128 (b,c) slices
#define LN_EPS 1e-5f

// Scratch (device globals: no allocation APIs allowed). 4 x 134 MB.
__device__ float g_left [NBATCH * SLICE];
__device__ float g_right[NBATCH * SLICE];
__device__ float g_og   [NBATCH * SLICE];
__device__ float g_tri  [NBATCH * SLICE];

__device__ __forceinline__ float fsigmoid(float v) {
    return 1.0f / (1.0f + __expf(-v));
}

// ---- packed f32x2 helpers ----
__device__ __forceinline__ unsigned long long dup2(float v) {
    unsigned long long r;
    asm("mov.b64 %0, {%1, %1};" : "=l"(r) : "f"(v));
    return r;
}
__device__ __forceinline__ unsigned long long fma2(unsigned long long a,
                                                   unsigned long long b,
                                                   unsigned long long c) {
    unsigned long long d;
    asm("fma.rn.f32x2 %0, %1, %2, %3;" : "=l"(d) : "l"(a), "l"(b), "l"(c));
    return d;
}
__device__ __forceinline__ float2 unpack2(unsigned long long v) {
    float2 r;
    asm("mov.b64 {%0, %1}, %2;" : "=f"(r.x), "=f"(r.y) : "l"(v));
    return r;
}

// ---------------------------------------------------------------------------
// Kernel 1: fused input LayerNorm + 5 projections.
// One block = 128 consecutive positions (fixed b,i; 128 consecutive k).
// Shared: xn transposed [64][132], weight tile [64][128], biases [128].
// Dynamic shared = (64*132 + 64*128 + 128) * 4 = 67072 bytes.
// ---------------------------------------------------------------------------
__global__ void __launch_bounds__(256, 2)
k_proj(const float* __restrict__ x,   const float* __restrict__ am,
       const float* __restrict__ lnw, const float* __restrict__ lnb,
       const float* __restrict__ Wlp, const float* __restrict__ blp,
       const float* __restrict__ Wrp, const float* __restrict__ brp,
       const float* __restrict__ Wlg, const float* __restrict__ blg,
       const float* __restrict__ Wrg, const float* __restrict__ brg,
       const float* __restrict__ Wog, const float* __restrict__ bog)
{
    extern __shared__ __align__(16) float sm[];
    float* xn = sm;                  // [64][132]   (channel-major, padded)
    float* Ws = sm + 64 * 132;       // [64][128]
    float* bs = Ws + 64 * 128;       // [128]

    const int tid  = threadIdx.x;
    const int posb = blockIdx.x * 128;
    const int b  = posb >> 18;             // / (512*512)
    const int i  = (posb >> 9) & (L_DIM - 1);
    const int kb = posb & (L_DIM - 1);     // multiple of 128
    const float mval = am[b * L_DIM + i];  // mask on the i (row) axis

    // ---- Phase A: LayerNorm, 2 threads per position ----
    {
        const int p    = tid >> 1;
        const int half = tid & 1;
        const float4* gx = reinterpret_cast<const float4*>(
            x + (size_t)(posb + p) * C_DIM + half * 32);
        float4 v[8];
#pragma unroll
        for (int q = 0; q < 8; q++) v[q] = gx[q];
        float s = 0.f, ss = 0.f;
#pragma unroll
        for (int q = 0; q < 8; q++) {
            s  += v[q].x + v[q].y + v[q].z + v[q].w;
            ss += v[q].x * v[q].x + v[q].y * v[q].y
                + v[q].z * v[q].z + v[q].w * v[q].w;
        }
        s  += __shfl_xor_sync(0xffffffffu, s, 1);
        ss += __shfl_xor_sync(0xffffffffu, ss, 1);
        const float mu   = s * (1.0f / 64.0f);
        const float rstd = rsqrtf(ss * (1.0f / 64.0f) - mu * mu + LN_EPS);
#pragma unroll
        for (int q = 0; q < 8; q++) {
            const int c0 = half * 32 + q * 4;
            xn[(c0 + 0) * 132 + p] = (v[q].x - mu) * rstd * lnw[c0 + 0] + lnb[c0 + 0];
            xn[(c0 + 1) * 132 + p] = (v[q].y - mu) * rstd * lnw[c0 + 1] + lnb[c0 + 1];
            xn[(c0 + 2) * 132 + p] = (v[q].z - mu) * rstd * lnw[c0 + 2] + lnb[c0 + 2];
            xn[(c0 + 3) * 132 + p] = (v[q].w - mu) * rstd * lnw[c0 + 3] + lnb[c0 + 3];
        }
    }
    __syncthreads();

    const int ty = tid >> 4, tx = tid & 15;
    const int r0 = ty * 8;          // 8 rows (positions) per thread
    const int c0 = tx * 4;          // 4 output channels per matrix

    // ---- Phases B0/B1: gated projections (lp|lg -> left), (rp|rg -> right) ----
#pragma unroll 1
    for (int pass = 0; pass < 2; pass++) {
        const float* Wa = pass ? Wrp : Wlp;
        const float* Wb = pass ? Wrg : Wlg;
        const float* ba = pass ? brp : blp;
        const float* bb = pass ? brg : blg;
        float* dst = pass ? g_right : g_left;

        // cooperative weight load: Ws[k][0:64]=Wa, Ws[k][64:128]=Wb
#pragma unroll
        for (int t = 0; t < 8; t++) {
            int q  = tid + t * 256;         // 2048 float4s
            int k  = q >> 5;
            int c4 = q & 31;
            float4 w = (c4 < 16)
                ? reinterpret_cast<const float4*>(Wa + k * 64)[c4]
                : reinterpret_cast<const float4*>(Wb + k * 64)[c4 - 16];
            reinterpret_cast<float4*>(Ws + k * 128)[c4] = w;
        }
        if (tid < 128) bs[tid] = (tid < 64) ? ba[tid] : bb[tid - 64];
        __syncthreads();

        // acc2[rr][p]: p=0,1 -> proj channel pairs, p=2,3 -> gate channel pairs
        unsigned long long acc2[8][4];
#pragma unroll
        for (int rr = 0; rr < 8; rr++)
#pragma unroll
            for (int p = 0; p < 4; p++) acc2[rr][p] = 0ull;

#pragma unroll 8
        for (int k = 0; k < 64; k++) {
            float4 a0 = *reinterpret_cast<const float4*>(xn + k * 132 + r0);
            float4 a1 = *reinterpret_cast<const float4*>(xn + k * 132 + r0 + 4);
            ulonglong2 bq0 = *reinterpret_cast<const ulonglong2*>(Ws + k * 128 + c0);
            ulonglong2 bq1 = *reinterpret_cast<const ulonglong2*>(Ws + k * 128 + 64 + c0);
            const unsigned long long bp[4] = {bq0.x, bq0.y, bq1.x, bq1.y};
            const float av[8] = {a0.x, a0.y, a0.z, a0.w, a1.x, a1.y, a1.z, a1.w};
#pragma unroll
            for (int rr = 0; rr < 8; rr++) {
                const unsigned long long a2 = dup2(av[rr]);
#pragma unroll
                for (int p = 0; p < 4; p++)
                    acc2[rr][p] = fma2(a2, bp[p], acc2[rr][p]);
            }
        }

        // unpack to [cc][rr]
        float pr[4][8], ga[4][8];
#pragma unroll
        for (int rr = 0; rr < 8; rr++) {
            float2 q0 = unpack2(acc2[rr][0]);
            float2 q1 = unpack2(acc2[rr][1]);
            float2 q2 = unpack2(acc2[rr][2]);
            float2 q3 = unpack2(acc2[rr][3]);
            pr[0][rr] = q0.x; pr[1][rr] = q0.y; pr[2][rr] = q1.x; pr[3][rr] = q1.y;
            ga[0][rr] = q2.x; ga[1][rr] = q2.y; ga[2][rr] = q3.x; ga[3][rr] = q3.y;
        }

        // epilogue: gated = (p + b) * mask * sigmoid(g + b'); store transposed
#pragma unroll
        for (int cc = 0; cc < 4; cc++) {
            const int c = c0 + cc;
            const float bp_ = bs[c], bg_ = bs[64 + c];
            float o[8];
#pragma unroll
            for (int rr = 0; rr < 8; rr++) {
                const float pv = pr[cc][rr] + bp_;
                const float gv = ga[cc][rr] + bg_;
                o[rr] = pv * mval * fsigmoid(gv);
            }
            float* d = dst + (size_t)(b * C_DIM + c) * SLICE
                           + (size_t)i * L_DIM + kb + r0;
            *reinterpret_cast<float4*>(d)     = make_float4(o[0], o[1], o[2], o[3]);
            *reinterpret_cast<float4*>(d + 4) = make_float4(o[4], o[5], o[6], o[7]);
        }
        __syncthreads();
    }

    // ---- Phase B2: out-gate projection (sigmoid, no mask) ----
    {
#pragma unroll
        for (int t = 0; t < 4; t++) {
            int q  = tid + t * 256;          // 1024 float4s
            int k  = q >> 4;
            int c4 = q & 15;
            reinterpret_cast<float4*>(Ws + k * 128)[c4] =
                reinterpret_cast<const float4*>(Wog + k * 64)[c4];
        }
        if (tid < 64) bs[tid] = bog[tid];
        __syncthreads();

        unsigned long long acc2[8][2];
#pragma unroll
        for (int rr = 0; rr < 8; rr++) { acc2[rr][0] = 0ull; acc2[rr][1] = 0ull; }

#pragma unroll 8
        for (int k = 0; k < 64; k++) {
            float4 a0 = *reinterpret_cast<const float4*>(xn + k * 132 + r0);
            float4 a1 = *reinterpret_cast<const float4*>(xn + k * 132 + r0 + 4);
            ulonglong2 bq0 = *reinterpret_cast<const ulonglong2*>(Ws + k * 128 + c0);
            const float av[8] = {a0.x, a0.y, a0.z, a0.w, a1.x, a1.y, a1.z, a1.w};
#pragma unroll
            for (int rr = 0; rr < 8; rr++) {
                const unsigned long long a2 = dup2(av[rr]);
                acc2[rr][0] = fma2(a2, bq0.x, acc2[rr][0]);
                acc2[rr][1] = fma2(a2, bq0.y, acc2[rr][1]);
            }
        }

        float pr[4][8];
#pragma unroll
        for (int rr = 0; rr < 8; rr++) {
            float2 q0 = unpack2(acc2[rr][0]);
            float2 q1 = unpack2(acc2[rr][1]);
            pr[0][rr] = q0.x; pr[1][rr] = q0.y; pr[2][rr] = q1.x; pr[3][rr] = q1.y;
        }

#pragma unroll
        for (int cc = 0; cc < 4; cc++) {
            const int c = c0 + cc;
            const float bo = bs[c];
            float o[8];
#pragma unroll
            for (int rr = 0; rr < 8; rr++)
                o[rr] = fsigmoid(pr[cc][rr] + bo);
            float* d = g_og + (size_t)(b * C_DIM + c) * SLICE
                            + (size_t)i * L_DIM + kb + r0;
            *reinterpret_cast<float4*>(d)     = make_float4(o[0], o[1], o[2], o[3]);
            *reinterpret_cast<float4*>(d + 4) = make_float4(o[4], o[5], o[6], o[7]);
        }
    }
}

// ---------------------------------------------------------------------------
// Kernel 2: batched NT SGEMM. tri = left @ right^T per (b,c) slice.
// 128 batches * 16 tiles of 128x128. BK=16, 8x8 thread tiles, double-buffered.
// Inner product uses fma.rn.f32x2 (32 packed FMAs per k-step per thread).
// ---------------------------------------------------------------------------
__global__ void __launch_bounds__(256, 2)
k_tri()
{
    __shared__ __align__(16) float As[2][16 * 132];
    __shared__ __align__(16) float Bs[2][16 * 132];

    const int tid   = threadIdx.x;
    const int batch = blockIdx.x >> 4;
    const int t4    = blockIdx.x & 15;
    const int i0    = (t4 >> 2) * 128;
    const int j0    = (t4 & 3) * 128;

    const float* __restrict__ A  = g_left  + (size_t)batch * SLICE;
    const float* __restrict__ Bm = g_right + (size_t)batch * SLICE;
    float* __restrict__ Cp       = g_tri   + (size_t)batch * SLICE;

    const int lrow = tid >> 2;   // 0..63 (rows lrow, lrow+64)
    const int lq   = tid & 3;    // which float4 in the 16-wide k-slab

    const int ty = tid >> 4, tx = tid & 15;
    const int r0  = ty * 8;
    const int cc0 = tx * 8;

    float4 ra0, ra1, rb0, rb1;

    // prologue: load k-block 0 and stage it
    ra0 = *reinterpret_cast<const float4*>(A  + (size_t)(i0 + lrow)      * L_DIM + lq * 4);
    ra1 = *reinterpret_cast<const float4*>(A  + (size_t)(i0 + lrow + 64) * L_DIM + lq * 4);
    rb0 = *reinterpret_cast<const float4*>(Bm + (size_t)(j0 + lrow)      * L_DIM + lq * 4);
    rb1 = *reinterpret_cast<const float4*>(Bm + (size_t)(j0 + lrow + 64) * L_DIM + lq * 4);
    {
        float* as = As[0];
        float* bsd = Bs[0];
        const float va0[4] = {ra0.x, ra0.y, ra0.z, ra0.w};
        const float va1[4] = {ra1.x, ra1.y, ra1.z, ra1.w};
        const float vb0[4] = {rb0.x, rb0.y, rb0.z, rb0.w};
        const float vb1[4] = {rb1.x, rb1.y, rb1.z, rb1.w};
#pragma unroll
        for (int e = 0; e < 4; e++) {
            const int kk = lq * 4 + e;
            as[kk * 132 + lrow]       = va0[e];
            as[kk * 132 + lrow + 64]  = va1[e];
            bsd[kk * 132 + lrow]      = vb0[e];
            bsd[kk * 132 + lrow + 64] = vb1[e];
        }
    }
    __syncthreads();

    unsigned long long acc2[8][4];
#pragma unroll
    for (int rr = 0; rr < 8; rr++)
#pragma unroll
        for (int p = 0; p < 4; p++) acc2[rr][p] = 0ull;

#pragma unroll 1
    for (int s = 0; s < 32; s++) {
        const int cur = s & 1;
        if (s + 1 < 32) {
            const int kb = (s + 1) * 16;
            ra0 = *reinterpret_cast<const float4*>(A  + (size_t)(i0 + lrow)      * L_DIM + kb + lq * 4);
            ra1 = *reinterpret_cast<const float4*>(A  + (size_t)(i0 + lrow + 64) * L_DIM + kb + lq * 4);
            rb0 = *reinterpret_cast<const float4*>(Bm + (size_t)(j0 + lrow)      * L_DIM + kb + lq * 4);
            rb1 = *reinterpret_cast<const float4*>(Bm + (size_t)(j0 + lrow + 64) * L_DIM + kb + lq * 4);
        }
        const float* as  = As[cur];
        const float* bsd = Bs[cur];
#pragma unroll
        for (int kk = 0; kk < 16; kk++) {
            float4 a0 = *reinterpret_cast<const float4*>(as + kk * 132 + r0);
            float4 a1 = *reinterpret_cast<const float4*>(as + kk * 132 + r0 + 4);
            ulonglong2 bq0 = *reinterpret_cast<const ulonglong2*>(bsd + kk * 132 + cc0);
            ulonglong2 bq1 = *reinterpret_cast<const ulonglong2*>(bsd + kk * 132 + cc0 + 4);
            const unsigned long long bp[4] = {bq0.x, bq0.y, bq1.x, bq1.y};
            const float av[8] = {a0.x, a0.y, a0.z, a0.w, a1.x, a1.y, a1.z, a1.w};
#pragma unroll
            for (int rr = 0; rr < 8; rr++) {
                const unsigned long long a2 = dup2(av[rr]);
#pragma unroll
                for (int p = 0; p < 4; p++)
                    acc2[rr][p] = fma2(a2, bp[p], acc2[rr][p]);
            }
        }
        if (s + 1 < 32) {
            const int nxt = cur ^ 1;
            float* asD = As[nxt];
            float* bsD = Bs[nxt];
            const float va0[4] = {ra0.x, ra0.y, ra0.z, ra0.w};
            const float va1[4] = {ra1.x, ra1.y, ra1.z, ra1.w};
            const float vb0[4] = {rb0.x, rb0.y, rb0.z, rb0.w};
            const float vb1[4] = {rb1.x, rb1.y, rb1.z, rb1.w};
#pragma unroll
            for (int e = 0; e < 4; e++) {
                const int kk = lq * 4 + e;
                asD[kk * 132 + lrow]       = va0[e];
                asD[kk * 132 + lrow + 64]  = va1[e];
                bsD[kk * 132 + lrow]       = vb0[e];
                bsD[kk * 132 + lrow + 64]  = vb1[e];
            }
            __syncthreads();
        }
    }

    // epilogue
#pragma unroll
    for (int rr = 0; rr < 8; rr++) {
        float2 q0 = unpack2(acc2[rr][0]);
        float2 q1 = unpack2(acc2[rr][1]);
        float2 q2 = unpack2(acc2[rr][2]);
        float2 q3 = unpack2(acc2[rr][3]);
        float* d = Cp + (size_t)(i0 + r0 + rr) * L_DIM + j0 + cc0;
        *reinterpret_cast<float4*>(d)     = make_float4(q0.x, q0.y, q1.x, q1.y);
        *reinterpret_cast<float4*>(d + 4) = make_float4(q2.x, q2.y, q3.x, q3.y);
    }
}

// ---------------------------------------------------------------------------
// Kernel 3: y = (LN(tri) * og) @ W_out + b_out + residual.
// One thread per (b,i,j); tri/og reads are coalesced over j ([b,c,i,j] layout).
// ---------------------------------------------------------------------------
__global__ void __launch_bounds__(256)
k_out(const float* __restrict__ x,
      const float* __restrict__ lnw, const float* __restrict__ lnb,
      const float* __restrict__ Wout, const float* __restrict__ bout,
      float* __restrict__ out)
{
    __shared__ __align__(16) float Ws[64 * 64];
    const int tid = threadIdx.x;
#pragma unroll
    for (int t = 0; t < 16; t++) Ws[tid + t * 256] = Wout[tid + t * 256];
    __syncthreads();

    const int bid = blockIdx.x;               // 2048 = b*1024 + i*2 + jc
    const int b  = bid >> 10;
    const int i  = (bid >> 1) & (L_DIM - 1);
    const int j  = ((bid & 1) << 8) + tid;

    const size_t pos   = ((size_t)(b * L_DIM + i) * L_DIM + j);
    const size_t tbase = (size_t)b * C_DIM * SLICE + (size_t)i * L_DIM + j;

    float t[64];
    float s = 0.f, ss = 0.f;
#pragma unroll
    for (int c = 0; c < 64; c++) {
        const float v = g_tri[tbase + (size_t)c * SLICE];
        t[c] = v;
        s += v;
        ss += v * v;
    }
    const float mu   = s * (1.0f / 64.0f);
    const float rstd = rsqrtf(ss * (1.0f / 64.0f) - mu * mu + LN_EPS);
#pragma unroll
    for (int c = 0; c < 64; c++) {
        const float og = g_og[tbase + (size_t)c * SLICE];
        t[c] = ((t[c] - mu) * rstd * lnw[c] + lnb[c]) * og;
    }

    const float4* resid = reinterpret_cast<const float4*>(x + pos * C_DIM);
    float4* o4          = reinterpret_cast<float4*>(out + pos * C_DIM);

#pragma unroll 1
    for (int h = 0; h < 2; h++) {
        unsigned long long acc2[16];
#pragma unroll
        for (int n = 0; n < 16; n++) acc2[n] = 0ull;
#pragma unroll
        for (int c = 0; c < 64; c++) {
            const unsigned long long tc = dup2(t[c]);
            const ulonglong2* wr =
                reinterpret_cast<const ulonglong2*>(Ws + c * 64 + h * 32);
#pragma unroll
            for (int n2 = 0; n2 < 8; n2++) {
                const ulonglong2 w = wr[n2];
                acc2[n2 * 2 + 0] = fma2(tc, w.x, acc2[n2 * 2 + 0]);
                acc2[n2 * 2 + 1] = fma2(tc, w.y, acc2[n2 * 2 + 1]);
            }
        }
#pragma unroll
        for (int n4 = 0; n4 < 8; n4++) {
            const int n = n4 * 4;
            const float2 p0 = unpack2(acc2[n4 * 2 + 0]);
            const float2 p1 = unpack2(acc2[n4 * 2 + 1]);
            const float4 r = resid[h * 8 + n4];
            o4[h * 8 + n4] = make_float4(
                p0.x + bout[h * 32 + n + 0] + r.x,
                p0.y + bout[h * 32 + n + 1] + r.y,
                p1.x + bout[h * 32 + n + 2] + r.z,
                p1.y + bout[h * 32 + n + 3] + r.w);
        }
    }
}

// ---------------------------------------------------------------------------
// Launch
// ---------------------------------------------------------------------------
extern "C" void kernel_launch(void* const* d_in, const int* in_sizes, int n_in,
                              void* d_out, int out_size)
{
    (void)in_sizes; (void)n_in; (void)out_size;
    const float* x    = (const float*)d_in[0];
    const float* am   = (const float*)d_in[1];
    const float* lniw = (const float*)d_in[2];
    const float* lnib = (const float*)d_in[3];
    const float* Wlp  = (const float*)d_in[4];
    const float* blp  = (const float*)d_in[5];
    const float* Wrp  = (const float*)d_in[6];
    const float* brp  = (const float*)d_in[7];
    const float* Wlg  = (const float*)d_in[8];
    const float* blg  = (const float*)d_in[9];
    const float* Wrg  = (const float*)d_in[10];
    const float* brg  = (const float*)d_in[11];
    const float* Wog  = (const float*)d_in[12];
    const float* bog  = (const float*)d_in[13];
    const float* lnow = (const float*)d_in[14];
    const float* lnob = (const float*)d_in[15];
    const float* Wout = (const float*)d_in[16];
    const float* bout = (const float*)d_in[17];
    float* out = (float*)d_out;

    const int smem1 = (64 * 132 + 64 * 128 + 128) * (int)sizeof(float); // 67072
    cudaFuncSetAttribute(k_proj, cudaFuncAttributeMaxDynamicSharedMemorySize, smem1);

    k_proj<<<4096, 256, smem1>>>(x, am, lniw, lnib,
                                 Wlp, blp, Wrp, brp,
                                 Wlg, blg, Wrg, brg,
                                 Wog, bog);
    k_tri<<<2048, 256>>>();
    k_out<<<2048, 256>>>(x, lnow, lnob, Wout, bout, out);
}

// round 5
// speedup vs baseline: 1.4240x; 1.4240x over previous
#include <cuda_runtime.h>
#include <cuda_bf16.h>
#include <cstddef>
#include <cstdint>

// ---------------------------------------------------------------------------
// RibonanzaNet pairwise mixer (outgoing triangle multiplication)
// B=2, L=512, C=64, fp32.
//
// NOTE: harness compiles PTX at .target sm_100 (no 'a') -> tcgen05 is
// unavailable. Tensor cores are reached via legacy mma.sync bf16 (sm_80+).
//
// Stage 1 (k_proj):  x = LN(in); 5 projections fused (f32x2 FFMA);
//                    left/right written as planar bf16 hi/lo [b,c,i,k].
// Stage 2 (k_tri):   tri[b,c,i,j] = sum_k left[b,c,i,k]*right[b,c,j,k]
//                    via mma.sync.m16n8k16 bf16 with bf16x3 compensation:
//                    tri = hi*hi + hi*lo + lo*hi (fp32 accum).
// Stage 3 (k_out):   y = (LN(tri) * og) @ W_out + b_out + residual.
// ---------------------------------------------------------------------------

#define L_DIM 512
#define C_DIM 64
#define SLICE (L_DIM * L_DIM)      // 262144
#define NBATCH (2 * C_DIM)         // 128 (b,c) slices
#define LN_EPS 1e-5f

__device__ unsigned short g_lhi[NBATCH * SLICE];   // left hi (bf16 bits)
__device__ unsigned short g_llo[NBATCH * SLICE];   // left lo
__device__ unsigned short g_rhi[NBATCH * SLICE];   // right hi
__device__ unsigned short g_rlo[NBATCH * SLICE];   // right lo
__device__ float          g_og [NBATCH * SLICE];
__device__ float          g_tri[NBATCH * SLICE];

__device__ __forceinline__ float fsigmoid(float v) {
    return 1.0f / (1.0f + __expf(-v));
}

// ---- packed f32x2 helpers ----
__device__ __forceinline__ unsigned long long dup2(float v) {
    unsigned long long r;
    asm("mov.b64 %0, {%1, %1};" : "=l"(r) : "f"(v));
    return r;
}
__device__ __forceinline__ unsigned long long fma2(unsigned long long a,
                                                   unsigned long long b,
                                                   unsigned long long c) {
    unsigned long long d;
    asm("fma.rn.f32x2 %0, %1, %2, %3;" : "=l"(d) : "l"(a), "l"(b), "l"(c));
    return d;
}
__device__ __forceinline__ float2 unpack2(unsigned long long v) {
    float2 r;
    asm("mov.b64 {%0, %1}, %2;" : "=f"(r.x), "=f"(r.y) : "l"(v));
    return r;
}

__device__ __forceinline__ uint32_t smem_u32(const void* p) {
    uint32_t a;
    asm("{ .reg .u64 t; cvta.to.shared.u64 t, %1; cvt.u32.u64 %0, t; }"
        : "=r"(a) : "l"(p));
    return a;
}
__device__ __forceinline__ void cp16(uint32_t s, const void* g) {
    asm volatile("cp.async.cg.shared.global [%0], [%1], 16;"
                 :: "r"(s), "l"(g) : "memory");
}
__device__ __forceinline__ void ldm_x4(uint32_t* r, uint32_t addr) {
    asm volatile("ldmatrix.sync.aligned.m8n8.x4.shared.b16 {%0,%1,%2,%3}, [%4];"
                 : "=r"(r[0]), "=r"(r[1]), "=r"(r[2]), "=r"(r[3]) : "r"(addr));
}
__device__ __forceinline__ void mma16816(float* c, const uint32_t* a,
                                         uint32_t b0, uint32_t b1) {
    asm volatile("mma.sync.aligned.m16n8k16.row.col.f32.bf16.bf16.f32 "
                 "{%0,%1,%2,%3}, {%4,%5,%6,%7}, {%8,%9}, {%0,%1,%2,%3};"
                 : "+f"(c[0]), "+f"(c[1]), "+f"(c[2]), "+f"(c[3])
                 : "r"(a[0]), "r"(a[1]), "r"(a[2]), "r"(a[3]), "r"(b0), "r"(b1));
}

// ---------------------------------------------------------------------------
// Kernel 1: fused input LayerNorm + 5 projections.
// ---------------------------------------------------------------------------
__global__ void __launch_bounds__(256, 2)
k_proj(const float* __restrict__ x,   const float* __restrict__ am,
       const float* __restrict__ lnw, const float* __restrict__ lnb,
       const float* __restrict__ Wlp, const float* __restrict__ blp,
       const float* __restrict__ Wrp, const float* __restrict__ brp,
       const float* __restrict__ Wlg, const float* __restrict__ blg,
       const float* __restrict__ Wrg, const float* __restrict__ brg,
       const float* __restrict__ Wog, const float* __restrict__ bog)
{
    extern __shared__ __align__(16) float sm[];
    float* xn = sm;                  // [64][132]
    float* Ws = sm + 64 * 132;       // [64][128]
    float* bs = Ws + 64 * 128;       // [128]

    const int tid  = threadIdx.x;
    const int posb = blockIdx.x * 128;
    const int b  = posb >> 18;
    const int i  = (posb >> 9) & (L_DIM - 1);
    const int kb = posb & (L_DIM - 1);
    const float mval = am[b * L_DIM + i];

    // ---- Phase A: LayerNorm, 2 threads per position ----
    {
        const int p    = tid >> 1;
        const int half = tid & 1;
        const float4* gx = reinterpret_cast<const float4*>(
            x + (size_t)(posb + p) * C_DIM + half * 32);
        float4 v[8];
#pragma unroll
        for (int q = 0; q < 8; q++) v[q] = gx[q];
        float s = 0.f, ss = 0.f;
#pragma unroll
        for (int q = 0; q < 8; q++) {
            s  += v[q].x + v[q].y + v[q].z + v[q].w;
            ss += v[q].x * v[q].x + v[q].y * v[q].y
                + v[q].z * v[q].z + v[q].w * v[q].w;
        }
        s  += __shfl_xor_sync(0xffffffffu, s, 1);
        ss += __shfl_xor_sync(0xffffffffu, ss, 1);
        const float mu   = s * (1.0f / 64.0f);
        const float rstd = rsqrtf(ss * (1.0f / 64.0f) - mu * mu + LN_EPS);
#pragma unroll
        for (int q = 0; q < 8; q++) {
            const int c0 = half * 32 + q * 4;
            xn[(c0 + 0) * 132 + p] = (v[q].x - mu) * rstd * lnw[c0 + 0] + lnb[c0 + 0];
            xn[(c0 + 1) * 132 + p] = (v[q].y - mu) * rstd * lnw[c0 + 1] + lnb[c0 + 1];
            xn[(c0 + 2) * 132 + p] = (v[q].z - mu) * rstd * lnw[c0 + 2] + lnb[c0 + 2];
            xn[(c0 + 3) * 132 + p] = (v[q].w - mu) * rstd * lnw[c0 + 3] + lnb[c0 + 3];
        }
    }
    __syncthreads();

    const int ty = tid >> 4, tx = tid & 15;
    const int r0 = ty * 8;
    const int c0 = tx * 4;

    // ---- Phases B0/B1: gated projections -> bf16 hi/lo ----
#pragma unroll 1
    for (int pass = 0; pass < 2; pass++) {
        const float* Wa = pass ? Wrp : Wlp;
        const float* Wb = pass ? Wrg : Wlg;
        const float* ba = pass ? brp : blp;
        const float* bb = pass ? brg : blg;

#pragma unroll
        for (int t = 0; t < 8; t++) {
            int q  = tid + t * 256;
            int k  = q >> 5;
            int c4 = q & 31;
            float4 w = (c4 < 16)
                ? reinterpret_cast<const float4*>(Wa + k * 64)[c4]
                : reinterpret_cast<const float4*>(Wb + k * 64)[c4 - 16];
            reinterpret_cast<float4*>(Ws + k * 128)[c4] = w;
        }
        if (tid < 128) bs[tid] = (tid < 64) ? ba[tid] : bb[tid - 64];
        __syncthreads();

        unsigned long long acc2[8][4];
#pragma unroll
        for (int rr = 0; rr < 8; rr++)
#pragma unroll
            for (int p = 0; p < 4; p++) acc2[rr][p] = 0ull;

#pragma unroll 8
        for (int k = 0; k < 64; k++) {
            float4 a0 = *reinterpret_cast<const float4*>(xn + k * 132 + r0);
            float4 a1 = *reinterpret_cast<const float4*>(xn + k * 132 + r0 + 4);
            ulonglong2 bq0 = *reinterpret_cast<const ulonglong2*>(Ws + k * 128 + c0);
            ulonglong2 bq1 = *reinterpret_cast<const ulonglong2*>(Ws + k * 128 + 64 + c0);
            const unsigned long long bp[4] = {bq0.x, bq0.y, bq1.x, bq1.y};
            const float av[8] = {a0.x, a0.y, a0.z, a0.w, a1.x, a1.y, a1.z, a1.w};
#pragma unroll
            for (int rr = 0; rr < 8; rr++) {
                const unsigned long long a2 = dup2(av[rr]);
#pragma unroll
                for (int p = 0; p < 4; p++)
                    acc2[rr][p] = fma2(a2, bp[p], acc2[rr][p]);
            }
        }

        float pr[4][8], ga[4][8];
#pragma unroll
        for (int rr = 0; rr < 8; rr++) {
            float2 q0 = unpack2(acc2[rr][0]);
            float2 q1 = unpack2(acc2[rr][1]);
            float2 q2 = unpack2(acc2[rr][2]);
            float2 q3 = unpack2(acc2[rr][3]);
            pr[0][rr] = q0.x; pr[1][rr] = q0.y; pr[2][rr] = q1.x; pr[3][rr] = q1.y;
            ga[0][rr] = q2.x; ga[1][rr] = q2.y; ga[2][rr] = q3.x; ga[3][rr] = q3.y;
        }

#pragma unroll
        for (int cc = 0; cc < 4; cc++) {
            const int c = c0 + cc;
            const float bp_ = bs[c], bg_ = bs[64 + c];
            __align__(16) __nv_bfloat16 hi[8];
            __align__(16) __nv_bfloat16 lo[8];
#pragma unroll
            for (int rr = 0; rr < 8; rr++) {
                const float pv = pr[cc][rr] + bp_;
                const float gv = ga[cc][rr] + bg_;
                const float o  = pv * mval * fsigmoid(gv);
                const __nv_bfloat16 h = __float2bfloat16(o);
                hi[rr] = h;
                lo[rr] = __float2bfloat16(o - __bfloat162float(h));
            }
            const size_t off = (size_t)(b * C_DIM + c) * SLICE
                             + (size_t)i * L_DIM + kb + r0;
            unsigned short* dh = (pass ? g_rhi : g_lhi) + off;
            unsigned short* dl = (pass ? g_rlo : g_llo) + off;
            *reinterpret_cast<uint4*>(dh) = *reinterpret_cast<uint4*>(hi);
            *reinterpret_cast<uint4*>(dl) = *reinterpret_cast<uint4*>(lo);
        }
        __syncthreads();
    }

    // ---- Phase B2: out-gate projection (fp32) ----
    {
#pragma unroll
        for (int t = 0; t < 4; t++) {
            int q  = tid + t * 256;
            int k  = q >> 4;
            int c4 = q & 15;
            reinterpret_cast<float4*>(Ws + k * 128)[c4] =
                reinterpret_cast<const float4*>(Wog + k * 64)[c4];
        }
        if (tid < 64) bs[tid] = bog[tid];
        __syncthreads();

        unsigned long long acc2[8][2];
#pragma unroll
        for (int rr = 0; rr < 8; rr++) { acc2[rr][0] = 0ull; acc2[rr][1] = 0ull; }

#pragma unroll 8
        for (int k = 0; k < 64; k++) {
            float4 a0 = *reinterpret_cast<const float4*>(xn + k * 132 + r0);
            float4 a1 = *reinterpret_cast<const float4*>(xn + k * 132 + r0 + 4);
            ulonglong2 bq0 = *reinterpret_cast<const ulonglong2*>(Ws + k * 128 + c0);
            const float av[8] = {a0.x, a0.y, a0.z, a0.w, a1.x, a1.y, a1.z, a1.w};
#pragma unroll
            for (int rr = 0; rr < 8; rr++) {
                const unsigned long long a2 = dup2(av[rr]);
                acc2[rr][0] = fma2(a2, bq0.x, acc2[rr][0]);
                acc2[rr][1] = fma2(a2, bq0.y, acc2[rr][1]);
            }
        }

        float pr[4][8];
#pragma unroll
        for (int rr = 0; rr < 8; rr++) {
            float2 q0 = unpack2(acc2[rr][0]);
            float2 q1 = unpack2(acc2[rr][1]);
            pr[0][rr] = q0.x; pr[1][rr] = q0.y; pr[2][rr] = q1.x; pr[3][rr] = q1.y;
        }

#pragma unroll
        for (int cc = 0; cc < 4; cc++) {
            const int c = c0 + cc;
            const float bo = bs[cc + c0];
            float o[8];
#pragma unroll
            for (int rr = 0; rr < 8; rr++)
                o[rr] = fsigmoid(pr[cc][rr] + bo);
            float* d = g_og + (size_t)(b * C_DIM + c) * SLICE
                            + (size_t)i * L_DIM + kb + r0;
            *reinterpret_cast<float4*>(d)     = make_float4(o[0], o[1], o[2], o[3]);
            *reinterpret_cast<float4*>(d + 4) = make_float4(o[4], o[5], o[6], o[7]);
        }
    }
}

// ---------------------------------------------------------------------------
// Kernel 2: batched NT GEMM via mma.sync bf16x3.
// Grid = 128 slices * 16 tiles of 128x128 = 2048 CTAs, 256 threads (8 warps).
// Warp tile 64x32 (m-tiles 4 x n-tiles 4 of m16n8k16).
// K staged in chunks of 32, cp.async double buffer.
// SMEM buffer layout (32KB each, 2 buffers):
//   +0     Ahi [128][32] bf16 (64B rows, chunk^=(row>>1)&3 swizzle)
//   +8192  Alo
//   +16384 Bhi
//   +24576 Blo
// ---------------------------------------------------------------------------
#define TRI_SMEM 65536

__global__ void __launch_bounds__(256, 1)
k_tri()
{
    extern __shared__ __align__(128) unsigned char smraw[];
    const uint32_t sbase = smem_u32(smraw);

    const int tid  = threadIdx.x;
    const int lane = tid & 31;
    const int wid  = tid >> 5;
    const int wm   = wid >> 2;      // 0..1
    const int wn   = wid & 3;       // 0..3

    const int batch = blockIdx.x >> 4;
    const int t     = blockIdx.x & 15;
    const int i0    = (t >> 2) * 128;
    const int j0    = (t & 3) * 128;

    const unsigned short* __restrict__ Ahi = g_lhi + (size_t)batch * SLICE + (size_t)i0 * L_DIM;
    const unsigned short* __restrict__ Alo = g_llo + (size_t)batch * SLICE + (size_t)i0 * L_DIM;
    const unsigned short* __restrict__ Bhi = g_rhi + (size_t)batch * SLICE + (size_t)j0 * L_DIM;
    const unsigned short* __restrict__ Blo = g_rlo + (size_t)batch * SLICE + (size_t)j0 * L_DIM;

    // per-thread cp.async offsets (2 x 16B chunks per matrix piece)
    uint32_t s_off[2], g_off[2];
#pragma unroll
    for (int t2 = 0; t2 < 2; t2++) {
        const int idx = tid + t2 * 256;     // 512 chunks
        const int row = idx >> 2;
        const int ch  = idx & 3;
        s_off[t2] = (uint32_t)(row * 64 + ((ch ^ ((row >> 1) & 3)) << 4));
        g_off[t2] = (uint32_t)(row * L_DIM + ch * 8);
    }

    // ldmatrix lane offsets (relative to buffer base)
    const int g = lane >> 3;
    uint32_t offA[2][4], offB[2][2];
#pragma unroll
    for (int ks = 0; ks < 2; ks++) {
#pragma unroll
        for (int mt = 0; mt < 4; mt++) {
            const int r  = wm * 64 + mt * 16 + ((g & 1) << 3) + (lane & 7);
            const int kc = ks * 2 + (g >> 1);
            offA[ks][mt] = (uint32_t)(r * 64 + ((kc ^ ((r >> 1) & 3)) << 4));
        }
#pragma unroll
        for (int np = 0; np < 2; np++) {
            const int r  = wn * 32 + np * 16 + ((g >> 1) << 3) + (lane & 7);
            const int kc = ks * 2 + (g & 1);
            offB[ks][np] = (uint32_t)(16384 + r * 64 + ((kc ^ ((r >> 1) & 3)) << 4));
        }
    }

    float acc[4][4][4];
#pragma unroll
    for (int mt = 0; mt < 4; mt++)
#pragma unroll
        for (int nt = 0; nt < 4; nt++)
#pragma unroll
            for (int e = 0; e < 4; e++) acc[mt][nt][e] = 0.f;

    // prologue: stage 0
    {
        const uint32_t sb = sbase;
#pragma unroll
        for (int t2 = 0; t2 < 2; t2++) {
            cp16(sb +         s_off[t2], Ahi + g_off[t2]);
            cp16(sb + 8192  + s_off[t2], Alo + g_off[t2]);
            cp16(sb + 16384 + s_off[t2], Bhi + g_off[t2]);
            cp16(sb + 24576 + s_off[t2], Blo + g_off[t2]);
        }
        asm volatile("cp.async.commit_group;" ::: "memory");
    }

#pragma unroll 1
    for (int s = 0; s < 16; s++) {
        if (s + 1 < 16) {
            const int kb = (s + 1) * 32;
            const uint32_t sb = sbase + ((s + 1) & 1) * 32768;
#pragma unroll
            for (int t2 = 0; t2 < 2; t2++) {
                cp16(sb +         s_off[t2], Ahi + kb + g_off[t2]);
                cp16(sb + 8192  + s_off[t2], Alo + kb + g_off[t2]);
                cp16(sb + 16384 + s_off[t2], Bhi + kb + g_off[t2]);
                cp16(sb + 24576 + s_off[t2], Blo + kb + g_off[t2]);
            }
            asm volatile("cp.async.commit_group;" ::: "memory");
            asm volatile("cp.async.wait_group 1;" ::: "memory");
        } else {
            asm volatile("cp.async.wait_group 0;" ::: "memory");
        }
        __syncthreads();

        const uint32_t bb = sbase + (s & 1) * 32768;
#pragma unroll
        for (int ks = 0; ks < 2; ks++) {
            uint32_t ah[4][4], al[4][4];
#pragma unroll
            for (int mt = 0; mt < 4; mt++) ldm_x4(ah[mt], bb + offA[ks][mt]);
#pragma unroll
            for (int mt = 0; mt < 4; mt++) ldm_x4(al[mt], bb + 8192 + offA[ks][mt]);
#pragma unroll
            for (int np = 0; np < 2; np++) {
                uint32_t bh[4], bl[4];
                ldm_x4(bh, bb + offB[ks][np]);
                ldm_x4(bl, bb + 8192 + offB[ks][np]);
#pragma unroll
                for (int mt = 0; mt < 4; mt++) {
                    float* a0 = acc[mt][np * 2];
                    float* a1 = acc[mt][np * 2 + 1];
                    mma16816(a0, ah[mt], bh[0], bh[1]);
                    mma16816(a0, ah[mt], bl[0], bl[1]);
                    mma16816(a0, al[mt], bh[0], bh[1]);
                    mma16816(a1, ah[mt], bh[2], bh[3]);
                    mma16816(a1, ah[mt], bl[2], bl[3]);
                    mma16816(a1, al[mt], bh[2], bh[3]);
                }
            }
        }
        __syncthreads();
    }

    // epilogue
    float* __restrict__ C = g_tri + (size_t)batch * SLICE;
    const int rb = i0 + wm * 64 + (lane >> 2);
    const int cb = j0 + wn * 32 + 2 * (lane & 3);
#pragma unroll
    for (int mt = 0; mt < 4; mt++) {
#pragma unroll
        for (int nt = 0; nt < 4; nt++) {
            const int r = rb + mt * 16;
            const int c = cb + nt * 8;
            *reinterpret_cast<float2*>(C + (size_t)r * L_DIM + c) =
                make_float2(acc[mt][nt][0], acc[mt][nt][1]);
            *reinterpret_cast<float2*>(C + (size_t)(r + 8) * L_DIM + c) =
                make_float2(acc[mt][nt][2], acc[mt][nt][3]);
        }
    }
}

// ---------------------------------------------------------------------------
// Kernel 3: y = (LN(tri) * og) @ W_out + b_out + residual.
// ---------------------------------------------------------------------------
__global__ void __launch_bounds__(256)
k_out(const float* __restrict__ x,
      const float* __restrict__ lnw, const float* __restrict__ lnb,
      const float* __restrict__ Wout, const float* __restrict__ bout,
      float* __restrict__ out)
{
    __shared__ __align__(16) float Ws[64 * 64];
    const int tid = threadIdx.x;
#pragma unroll
    for (int t = 0; t < 16; t++) Ws[tid + t * 256] = Wout[tid + t * 256];
    __syncthreads();

    const int bid = blockIdx.x;
    const int b  = bid >> 10;
    const int i  = (bid >> 1) & (L_DIM - 1);
    const int j  = ((bid & 1) << 8) + tid;

    const size_t pos   = ((size_t)(b * L_DIM + i) * L_DIM + j);
    const size_t tbase = (size_t)b * C_DIM * SLICE + (size_t)i * L_DIM + j;

    float t[64];
    float s = 0.f, ss = 0.f;
#pragma unroll
    for (int c = 0; c < 64; c++) {
        const float v = g_tri[tbase + (size_t)c * SLICE];
        t[c] = v;
        s += v;
        ss += v * v;
    }
    const float mu   = s * (1.0f / 64.0f);
    const float rstd = rsqrtf(ss * (1.0f / 64.0f) - mu * mu + LN_EPS);
#pragma unroll
    for (int c = 0; c < 64; c++) {
        const float og = g_og[tbase + (size_t)c * SLICE];
        t[c] = ((t[c] - mu) * rstd * lnw[c] + lnb[c]) * og;
    }

    const float4* resid = reinterpret_cast<const float4*>(x + pos * C_DIM);
    float4* o4          = reinterpret_cast<float4*>(out + pos * C_DIM);

#pragma unroll 1
    for (int h = 0; h < 2; h++) {
        unsigned long long acc2[16];
#pragma unroll
        for (int n = 0; n < 16; n++) acc2[n] = 0ull;
#pragma unroll
        for (int c = 0; c < 64; c++) {
            const unsigned long long tc = dup2(t[c]);
            const ulonglong2* wr =
                reinterpret_cast<const ulonglong2*>(Ws + c * 64 + h * 32);
#pragma unroll
            for (int n2 = 0; n2 < 8; n2++) {
                const ulonglong2 w = wr[n2];
                acc2[n2 * 2 + 0] = fma2(tc, w.x, acc2[n2 * 2 + 0]);
                acc2[n2 * 2 + 1] = fma2(tc, w.y, acc2[n2 * 2 + 1]);
            }
        }
#pragma unroll
        for (int n4 = 0; n4 < 8; n4++) {
            const int n = n4 * 4;
            const float2 p0 = unpack2(acc2[n4 * 2 + 0]);
            const float2 p1 = unpack2(acc2[n4 * 2 + 1]);
            const float4 r = resid[h * 8 + n4];
            o4[h * 8 + n4] = make_float4(
                p0.x + bout[h * 32 + n + 0] + r.x,
                p0.y + bout[h * 32 + n + 1] + r.y,
                p1.x + bout[h * 32 + n + 2] + r.z,
                p1.y + bout[h * 32 + n + 3] + r.w);
        }
    }
}

// ---------------------------------------------------------------------------
// Launch
// ---------------------------------------------------------------------------
extern "C" void kernel_launch(void* const* d_in, const int* in_sizes, int n_in,
                              void* d_out, int out_size)
{
    (void)in_sizes; (void)n_in; (void)out_size;
    const float* x    = (const float*)d_in[0];
    const float* am   = (const float*)d_in[1];
    const float* lniw = (const float*)d_in[2];
    const float* lnib = (const float*)d_in[3];
    const float* Wlp  = (const float*)d_in[4];
    const float* blp  = (const float*)d_in[5];
    const float* Wrp  = (const float*)d_in[6];
    const float* brp  = (const float*)d_in[7];
    const float* Wlg  = (const float*)d_in[8];
    const float* blg  = (const float*)d_in[9];
    const float* Wrg  = (const float*)d_in[10];
    const float* brg  = (const float*)d_in[11];
    const float* Wog  = (const float*)d_in[12];
    const float* bog  = (const float*)d_in[13];
    const float* lnow = (const float*)d_in[14];
    const float* lnob = (const float*)d_in[15];
    const float* Wout = (const float*)d_in[16];
    const float* bout = (const float*)d_in[17];
    float* out = (float*)d_out;

    const int smem1 = (64 * 132 + 64 * 128 + 128) * (int)sizeof(float); // 67072
    cudaFuncSetAttribute(k_proj, cudaFuncAttributeMaxDynamicSharedMemorySize, smem1);
    cudaFuncSetAttribute(k_tri,  cudaFuncAttributeMaxDynamicSharedMemorySize, TRI_SMEM);

    k_proj<<<4096, 256, smem1>>>(x, am, lniw, lnib,
                                 Wlp, blp, Wrp, brp,
                                 Wlg, blg, Wrg, brg,
                                 Wog, bog);
    k_tri<<<2048, 256, TRI_SMEM>>>();
    k_out<<<2048, 256>>>(x, lnow, lnob, Wout, bout, out);
}

// round 7
// speedup vs baseline: 1.4861x; 1.0436x over previous
#include <cuda_runtime.h>
#include <cuda_bf16.h>
#include <cstddef>
#include <cstdint>

// ---------------------------------------------------------------------------
// RibonanzaNet pairwise mixer (outgoing triangle multiplication)
// B=2, L=512, C=64, fp32.  Target: sm_100 (no 'a') -> mma.sync bf16 path.
//
// k_prep:  split+transpose weights to bf16 hi/lo, lp/lg + rp/rg interleaved.
// k_proj:  LN(x) -> bf16 hi/lo SMEM; 3 tensor-core passes (L,R,O) with
//          bf16x3 compensation; epilogues gated in-register; outputs
//          transposed planar [b,c,i,k]: left/right bf16 hi/lo, og fp32.
// k_tri:   tri = left @ right^T per (b,c) slice, mma.sync bf16x3.
// k_out:   y = (LN(tri) * og) @ W_out + b_out + residual.
// ---------------------------------------------------------------------------

#define L_DIM 512
#define C_DIM 64
#define SLICE (L_DIM * L_DIM)      // 262144
#define NBATCH (2 * C_DIM)         // 128
#define LN_EPS 1e-5f

__device__ unsigned short g_lhi[NBATCH * SLICE];
__device__ unsigned short g_llo[NBATCH * SLICE];
__device__ unsigned short g_rhi[NBATCH * SLICE];
__device__ unsigned short g_rlo[NBATCH * SLICE];
__device__ float          g_og [NBATCH * SLICE];
__device__ float          g_tri[NBATCH * SLICE];

// prepped weights: [hi/lo][n][k] bf16 bits; L/R interleaved (2c->proj, 2c+1->gate)
__device__ unsigned short g_WL[2 * 128 * 64];
__device__ unsigned short g_WR[2 * 128 * 64];
__device__ unsigned short g_WO[2 * 64 * 64];

__device__ __forceinline__ float fsigmoid(float v) {
    return 1.0f / (1.0f + __expf(-v));
}
__device__ __forceinline__ void split_bf16(float v, unsigned short& h, unsigned short& l) {
    __nv_bfloat16 hh = __float2bfloat16(v);
    h = __bfloat16_as_ushort(hh);
    l = __bfloat16_as_ushort(__float2bfloat16(v - __bfloat162float(hh)));
}

// ---- packed f32x2 helpers (k_out) ----
__device__ __forceinline__ unsigned long long dup2(float v) {
    unsigned long long r;
    asm("mov.b64 %0, {%1, %1};" : "=l"(r) : "f"(v));
    return r;
}
__device__ __forceinline__ unsigned long long fma2(unsigned long long a,
                                                   unsigned long long b,
                                                   unsigned long long c) {
    unsigned long long d;
    asm("fma.rn.f32x2 %0, %1, %2, %3;" : "=l"(d) : "l"(a), "l"(b), "l"(c));
    return d;
}
__device__ __forceinline__ float2 unpack2(unsigned long long v) {
    float2 r;
    asm("mov.b64 {%0, %1}, %2;" : "=f"(r.x), "=f"(r.y) : "l"(v));
    return r;
}

__device__ __forceinline__ uint32_t smem_u32(const void* p) {
    uint32_t a;
    asm("{ .reg .u64 t; cvta.to.shared.u64 t, %1; cvt.u32.u64 %0, t; }"
        : "=r"(a) : "l"(p));
    return a;
}
__device__ __forceinline__ void cp16(uint32_t s, const void* g) {
    asm volatile("cp.async.cg.shared.global [%0], [%1], 16;"
                 :: "r"(s), "l"(g) : "memory");
}
__device__ __forceinline__ void ldm_x4(uint32_t* r, uint32_t addr) {
    asm volatile("ldmatrix.sync.aligned.m8n8.x4.shared.b16 {%0,%1,%2,%3}, [%4];"
                 : "=r"(r[0]), "=r"(r[1]), "=r"(r[2]), "=r"(r[3]) : "r"(addr));
}
__device__ __forceinline__ void mma16816(float* c, const uint32_t* a,
                                         uint32_t b0, uint32_t b1) {
    asm volatile("mma.sync.aligned.m16n8k16.row.col.f32.bf16.bf16.f32 "
                 "{%0,%1,%2,%3}, {%4,%5,%6,%7}, {%8,%9}, {%0,%1,%2,%3};"
                 : "+f"(c[0]), "+f"(c[1]), "+f"(c[2]), "+f"(c[3])
                 : "r"(a[0]), "r"(a[1]), "r"(a[2]), "r"(a[3]), "r"(b0), "r"(b1));
}

// ---------------------------------------------------------------------------
// Kernel 0: weight prep (transpose to [n][k], bf16 hi/lo split, interleave).
// ---------------------------------------------------------------------------
__global__ void k_prep(const float* __restrict__ Wlp, const float* __restrict__ Wlg,
                       const float* __restrict__ Wrp, const float* __restrict__ Wrg,
                       const float* __restrict__ Wog)
{
    const int tid = threadIdx.x;
    for (int idx = tid; idx < 128 * 64; idx += 256) {
        const int n = idx >> 6, k = idx & 63, c = n >> 1;
        unsigned short h, l;
        const float wl = (n & 1) ? Wlg[k * 64 + c] : Wlp[k * 64 + c];
        split_bf16(wl, h, l);
        g_WL[idx] = h; g_WL[8192 + idx] = l;
        const float wr = (n & 1) ? Wrg[k * 64 + c] : Wrp[k * 64 + c];
        split_bf16(wr, h, l);
        g_WR[idx] = h; g_WR[8192 + idx] = l;
    }
    for (int idx = tid; idx < 64 * 64; idx += 256) {
        const int n = idx >> 6, k = idx & 63;
        unsigned short h, l;
        split_bf16(Wog[k * 64 + n], h, l);
        g_WO[idx] = h; g_WO[4096 + idx] = l;
    }
}

// ---------------------------------------------------------------------------
// Kernel 1: fused LN + 5 projections on tensor cores.
// Block = 128 positions (fixed b,i; k in [kb,kb+128)), 256 threads, 8 warps.
// SMEM: A hi/lo [128 x 64] bf16 (16KB each), B hi/lo (16KB each),
//       staging 32KB.  Total 98304.
// Swizzle (128B rows, 8 chunks of 16B): cc ^= row & 7.
// ---------------------------------------------------------------------------
#define PA_HI 0
#define PA_LO 16384
#define PB_HI 32768
#define PB_LO 49152
#define PSTG  65536
#define PROJ_SMEM 98304

template<int NT8>   // n8-tiles per warp: 4 (L/R: warp n32) or 2 (O: warp n16)
__device__ __forceinline__ void proj_mma(uint32_t sb, int wm, int wn, int lane,
                                         float (&acc)[4][NT8][4])
{
    const int g = lane >> 3;
#pragma unroll
    for (int mt = 0; mt < 4; mt++)
#pragma unroll
        for (int t = 0; t < NT8; t++)
#pragma unroll
            for (int e = 0; e < 4; e++) acc[mt][t][e] = 0.f;

#pragma unroll
    for (int ks = 0; ks < 4; ks++) {
        uint32_t ah[4][4], al[4][4];
#pragma unroll
        for (int mt = 0; mt < 4; mt++) {
            const int r  = wm * 64 + mt * 16 + ((g & 1) << 3) + (lane & 7);
            const int kc = 2 * ks + (g >> 1);
            const uint32_t addr = sb + PA_HI + r * 128 + ((kc ^ (r & 7)) << 4);
            ldm_x4(ah[mt], addr);
            ldm_x4(al[mt], addr + 16384);
        }
#pragma unroll
        for (int np = 0; np < NT8 / 2; np++) {
            const int n  = NT8 * 8 * wn + 16 * np + ((g >> 1) << 3) + (lane & 7);
            const int kc = 2 * ks + (g & 1);
            const uint32_t baddr = sb + PB_HI + n * 128 + ((kc ^ (n & 7)) << 4);
            uint32_t bh[4], bl[4];
            ldm_x4(bh, baddr);
            ldm_x4(bl, baddr + 16384);
#pragma unroll
            for (int mt = 0; mt < 4; mt++) {
                float* a0 = acc[mt][np * 2];
                float* a1 = acc[mt][np * 2 + 1];
                mma16816(a0, ah[mt], bh[0], bh[1]);
                mma16816(a0, ah[mt], bl[0], bl[1]);
                mma16816(a0, al[mt], bh[0], bh[1]);
                mma16816(a1, ah[mt], bh[2], bh[3]);
                mma16816(a1, ah[mt], bl[2], bl[3]);
                mma16816(a1, al[mt], bh[2], bh[3]);
            }
        }
    }
}

// issue cp.async for a [ROWS x 64] hi/lo pair from prepped weights
template<int ROWS>
__device__ __forceinline__ void proj_loadB(uint32_t sb, const unsigned short* src,
                                           int losrc_off, int tid)
{
#pragma unroll
    for (int t = 0; t < ROWS / 32; t++) {
        const int idx = tid + t * 256;      // ROWS*8 chunks
        const int row = idx >> 3;
        const int cc  = idx & 7;
        const uint32_t so = row * 128 + ((cc ^ (row & 7)) << 4);
        cp16(sb + PB_HI + so, src + row * 64 + cc * 8);
        cp16(sb + PB_LO + so, src + losrc_off + row * 64 + cc * 8);
    }
    asm volatile("cp.async.commit_group;" ::: "memory");
}

__global__ void __launch_bounds__(256)
k_proj(const float* __restrict__ x,   const float* __restrict__ am,
       const float* __restrict__ lnw, const float* __restrict__ lnb,
       const float* __restrict__ blp, const float* __restrict__ blg,
       const float* __restrict__ brp, const float* __restrict__ brg,
       const float* __restrict__ bog)
{
    extern __shared__ __align__(128) unsigned char smraw[];
    const uint32_t sb = smem_u32(smraw);

    const int tid  = threadIdx.x;
    const int lane = tid & 31;
    const int wid  = tid >> 5;
    const int wm   = wid >> 2;      // 0..1
    const int wn   = wid & 3;       // 0..3

    const int posb = blockIdx.x * 128;
    const int b  = posb >> 18;
    const int i  = (posb >> 9) & (L_DIM - 1);
    const int kb = posb & (L_DIM - 1);
    const float mval = am[b * L_DIM + i];

    // pass-L weights in flight immediately
    proj_loadB<128>(sb, g_WL, 8192, tid);

    // ---- LN phase: 2 threads per position; write A hi/lo (swizzled bf16) ----
    {
        const int p    = tid >> 1;
        const int half = tid & 1;
        const float4* gx = reinterpret_cast<const float4*>(
            x + (size_t)(posb + p) * C_DIM + half * 32);
        float4 v[8];
#pragma unroll
        for (int q = 0; q < 8; q++) v[q] = gx[q];
        float s = 0.f, ss = 0.f;
#pragma unroll
        for (int q = 0; q < 8; q++) {
            s  += v[q].x + v[q].y + v[q].z + v[q].w;
            ss += v[q].x * v[q].x + v[q].y * v[q].y
                + v[q].z * v[q].z + v[q].w * v[q].w;
        }
        s  += __shfl_xor_sync(0xffffffffu, s, 1);
        ss += __shfl_xor_sync(0xffffffffu, ss, 1);
        const float mu   = s * (1.0f / 64.0f);
        const float rstd = rsqrtf(ss * (1.0f / 64.0f) - mu * mu + LN_EPS);
#pragma unroll
        for (int q = 0; q < 8; q++) {
            const int c0 = half * 32 + q * 4;
            float nv[4] = {
                (v[q].x - mu) * rstd * lnw[c0 + 0] + lnb[c0 + 0],
                (v[q].y - mu) * rstd * lnw[c0 + 1] + lnb[c0 + 1],
                (v[q].z - mu) * rstd * lnw[c0 + 2] + lnb[c0 + 2],
                (v[q].w - mu) * rstd * lnw[c0 + 3] + lnb[c0 + 3]};
            unsigned short h[4], l[4];
#pragma unroll
            for (int e = 0; e < 4; e++) split_bf16(nv[e], h[e], l[e]);
            const int cc = 4 * half + (q >> 1);
            const uint32_t addr = p * 128 + ((cc ^ (p & 7)) << 4) + (q & 1) * 8;
            *reinterpret_cast<uint2*>(smraw + PA_HI + addr) =
                make_uint2((uint32_t)h[0] | ((uint32_t)h[1] << 16),
                           (uint32_t)h[2] | ((uint32_t)h[3] << 16));
            *reinterpret_cast<uint2*>(smraw + PA_LO + addr) =
                make_uint2((uint32_t)l[0] | ((uint32_t)l[1] << 16),
                           (uint32_t)l[2] | ((uint32_t)l[3] << 16));
        }
    }
    asm volatile("cp.async.wait_group 0;" ::: "memory");
    __syncthreads();

    unsigned short* stgH = reinterpret_cast<unsigned short*>(smraw + PSTG);
    unsigned short* stgL = reinterpret_cast<unsigned short*>(smraw + PSTG + 16384);

    // ================= passes L and R =================
#pragma unroll 1
    for (int pass = 0; pass < 2; pass++) {
        float acc[4][4][4];
        proj_mma<4>(sb, wm, wn, lane, acc);
        __syncthreads();                       // B consumed

        if (pass == 0) proj_loadB<128>(sb, g_WR, 8192, tid);
        else           proj_loadB<64>(sb, g_WO, 4096, tid);

        // epilogue: per lane, (P,G) pairs for channel ch
        const float* Bp = pass ? brp : blp;
        const float* Bg = pass ? brg : blg;
        float bp[4], bg[4];
#pragma unroll
        for (int t = 0; t < 4; t++) {
            const int ch = 16 * wn + 4 * t + (lane & 3);
            bp[t] = Bp[ch];
            bg[t] = Bg[ch];
        }
#pragma unroll
        for (int mt = 0; mt < 4; mt++) {
            const int r = wm * 64 + mt * 16 + (lane >> 2);
#pragma unroll
            for (int t = 0; t < 4; t++) {
                const int ch = 16 * wn + 4 * t + (lane & 3);
                const float o0 = (acc[mt][t][0] + bp[t]) * mval
                               * fsigmoid(acc[mt][t][1] + bg[t]);
                const float o1 = (acc[mt][t][2] + bp[t]) * mval
                               * fsigmoid(acc[mt][t][3] + bg[t]);
                unsigned short h0, l0, h1, l1;
                split_bf16(o0, h0, l0);
                split_bf16(o1, h1, l1);
                stgH[ch * 128 + r]     = h0;
                stgH[ch * 128 + r + 8] = h1;
                stgL[ch * 128 + r]     = l0;
                stgL[ch * 128 + r + 8] = l1;
            }
        }
        __syncthreads();

        // coalesced global store from staging
        unsigned short* dH = pass ? g_rhi : g_lhi;
        unsigned short* dL = pass ? g_rlo : g_llo;
#pragma unroll
        for (int q = 0; q < 8; q++) {
            const int idx  = tid + q * 256;    // 2048 chunks
            const int half = idx >> 10;
            const int rem  = idx & 1023;
            const int ch   = rem >> 4;
            const int cc   = rem & 15;
            const uint4 v = *reinterpret_cast<const uint4*>(
                smraw + PSTG + half * 16384 + rem * 16);
            unsigned short* d = (half ? dL : dH)
                + (size_t)(b * C_DIM + ch) * SLICE + (size_t)i * L_DIM + kb + cc * 8;
            *reinterpret_cast<uint4*>(d) = v;
        }
        asm volatile("cp.async.wait_group 0;" ::: "memory");
        __syncthreads();                       // staging consumed + next B ready
    }

    // ================= pass O (out-gate, fp32) =================
    {
        float acc[4][2][4];
        proj_mma<2>(sb, wm, wn, lane, acc);

        float* stgF = reinterpret_cast<float*>(smraw + PSTG);
#pragma unroll
        for (int mt = 0; mt < 4; mt++) {
            const int r = wm * 64 + mt * 16 + (lane >> 2);
#pragma unroll
            for (int t = 0; t < 2; t++) {
                const int ch0 = 16 * wn + 8 * t + 2 * (lane & 3);
                stgF[ch0 * 128 + r]           = fsigmoid(acc[mt][t][0] + bog[ch0]);
                stgF[(ch0 + 1) * 128 + r]     = fsigmoid(acc[mt][t][1] + bog[ch0 + 1]);
                stgF[ch0 * 128 + r + 8]       = fsigmoid(acc[mt][t][2] + bog[ch0]);
                stgF[(ch0 + 1) * 128 + r + 8] = fsigmoid(acc[mt][t][3] + bog[ch0 + 1]);
            }
        }
        __syncthreads();

#pragma unroll
        for (int q = 0; q < 8; q++) {
            const int idx = tid + q * 256;     // 2048 chunks
            const int ch  = idx >> 5;
            const int cc  = idx & 31;
            const uint4 v = reinterpret_cast<const uint4*>(smraw + PSTG)[idx];
            float* d = g_og + (size_t)(b * C_DIM + ch) * SLICE
                     + (size_t)i * L_DIM + kb + cc * 4;
            *reinterpret_cast<uint4*>(d) = v;
        }
    }
}

// ---------------------------------------------------------------------------
// Kernel 2: batched NT GEMM via mma.sync bf16x3 (unchanged from R5-pass).
// ---------------------------------------------------------------------------
#define TRI_SMEM 65536

__global__ void __launch_bounds__(256, 1)
k_tri()
{
    extern __shared__ __align__(128) unsigned char smraw[];
    const uint32_t sbase = smem_u32(smraw);

    const int tid  = threadIdx.x;
    const int lane = tid & 31;
    const int wid  = tid >> 5;
    const int wm   = wid >> 2;
    const int wn   = wid & 3;

    const int batch = blockIdx.x >> 4;
    const int t     = blockIdx.x & 15;
    const int i0    = (t >> 2) * 128;
    const int j0    = (t & 3) * 128;

    const unsigned short* __restrict__ Ahi = g_lhi + (size_t)batch * SLICE + (size_t)i0 * L_DIM;
    const unsigned short* __restrict__ Alo = g_llo + (size_t)batch * SLICE + (size_t)i0 * L_DIM;
    const unsigned short* __restrict__ Bhi = g_rhi + (size_t)batch * SLICE + (size_t)j0 * L_DIM;
    const unsigned short* __restrict__ Blo = g_rlo + (size_t)batch * SLICE + (size_t)j0 * L_DIM;

    uint32_t s_off[2], g_off[2];
#pragma unroll
    for (int t2 = 0; t2 < 2; t2++) {
        const int idx = tid + t2 * 256;
        const int row = idx >> 2;
        const int ch  = idx & 3;
        s_off[t2] = (uint32_t)(row * 64 + ((ch ^ ((row >> 1) & 3)) << 4));
        g_off[t2] = (uint32_t)(row * L_DIM + ch * 8);
    }

    const int g = lane >> 3;
    uint32_t offA[2][4], offB[2][2];
#pragma unroll
    for (int ks = 0; ks < 2; ks++) {
#pragma unroll
        for (int mt = 0; mt < 4; mt++) {
            const int r  = wm * 64 + mt * 16 + ((g & 1) << 3) + (lane & 7);
            const int kc = ks * 2 + (g >> 1);
            offA[ks][mt] = (uint32_t)(r * 64 + ((kc ^ ((r >> 1) & 3)) << 4));
        }
#pragma unroll
        for (int np = 0; np < 2; np++) {
            const int r  = wn * 32 + np * 16 + ((g >> 1) << 3) + (lane & 7);
            const int kc = ks * 2 + (g & 1);
            offB[ks][np] = (uint32_t)(16384 + r * 64 + ((kc ^ ((r >> 1) & 3)) << 4));
        }
    }

    float acc[4][4][4];
#pragma unroll
    for (int mt = 0; mt < 4; mt++)
#pragma unroll
        for (int nt = 0; nt < 4; nt++)
#pragma unroll
            for (int e = 0; e < 4; e++) acc[mt][nt][e] = 0.f;

    {
        const uint32_t sb = sbase;
#pragma unroll
        for (int t2 = 0; t2 < 2; t2++) {
            cp16(sb +         s_off[t2], Ahi + g_off[t2]);
            cp16(sb + 8192  + s_off[t2], Alo + g_off[t2]);
            cp16(sb + 16384 + s_off[t2], Bhi + g_off[t2]);
            cp16(sb + 24576 + s_off[t2], Blo + g_off[t2]);
        }
        asm volatile("cp.async.commit_group;" ::: "memory");
    }

#pragma unroll 1
    for (int s = 0; s < 16; s++) {
        if (s + 1 < 16) {
            const int kb = (s + 1) * 32;
            const uint32_t sb = sbase + ((s + 1) & 1) * 32768;
#pragma unroll
            for (int t2 = 0; t2 < 2; t2++) {
                cp16(sb +         s_off[t2], Ahi + kb + g_off[t2]);
                cp16(sb + 8192  + s_off[t2], Alo + kb + g_off[t2]);
                cp16(sb + 16384 + s_off[t2], Bhi + kb + g_off[t2]);
                cp16(sb + 24576 + s_off[t2], Blo + kb + g_off[t2]);
            }
            asm volatile("cp.async.commit_group;" ::: "memory");
            asm volatile("cp.async.wait_group 1;" ::: "memory");
        } else {
            asm volatile("cp.async.wait_group 0;" ::: "memory");
        }
        __syncthreads();

        const uint32_t bb = sbase + (s & 1) * 32768;
#pragma unroll
        for (int ks = 0; ks < 2; ks++) {
            uint32_t ah[4][4], al[4][4];
#pragma unroll
            for (int mt = 0; mt < 4; mt++) ldm_x4(ah[mt], bb + offA[ks][mt]);
#pragma unroll
            for (int mt = 0; mt < 4; mt++) ldm_x4(al[mt], bb + 8192 + offA[ks][mt]);
#pragma unroll
            for (int np = 0; np < 2; np++) {
                uint32_t bh[4], bl[4];
                ldm_x4(bh, bb + offB[ks][np]);
                ldm_x4(bl, bb + 8192 + offB[ks][np]);
#pragma unroll
                for (int mt = 0; mt < 4; mt++) {
                    float* a0 = acc[mt][np * 2];
                    float* a1 = acc[mt][np * 2 + 1];
                    mma16816(a0, ah[mt], bh[0], bh[1]);
                    mma16816(a0, ah[mt], bl[0], bl[1]);
                    mma16816(a0, al[mt], bh[0], bh[1]);
                    mma16816(a1, ah[mt], bh[2], bh[3]);
                    mma16816(a1, ah[mt], bl[2], bl[3]);
                    mma16816(a1, al[mt], bh[2], bh[3]);
                }
            }
        }
        __syncthreads();
    }

    float* __restrict__ C = g_tri + (size_t)batch * SLICE;
    const int rb = i0 + wm * 64 + (lane >> 2);
    const int cb = j0 + wn * 32 + 2 * (lane & 3);
#pragma unroll
    for (int mt = 0; mt < 4; mt++) {
#pragma unroll
        for (int nt = 0; nt < 4; nt++) {
            const int r = rb + mt * 16;
            const int c = cb + nt * 8;
            *reinterpret_cast<float2*>(C + (size_t)r * L_DIM + c) =
                make_float2(acc[mt][nt][0], acc[mt][nt][1]);
            *reinterpret_cast<float2*>(C + (size_t)(r + 8) * L_DIM + c) =
                make_float2(acc[mt][nt][2], acc[mt][nt][3]);
        }
    }
}

// ---------------------------------------------------------------------------
// Kernel 3: y = (LN(tri) * og) @ W_out + b_out + residual.
// ---------------------------------------------------------------------------
__global__ void __launch_bounds__(256)
k_out(const float* __restrict__ x,
      const float* __restrict__ lnw, const float* __restrict__ lnb,
      const float* __restrict__ Wout, const float* __restrict__ bout,
      float* __restrict__ out)
{
    __shared__ __align__(16) float Ws[64 * 64];
    const int tid = threadIdx.x;
#pragma unroll
    for (int t = 0; t < 16; t++) Ws[tid + t * 256] = Wout[tid + t * 256];
    __syncthreads();

    const int bid = blockIdx.x;
    const int b  = bid >> 10;
    const int i  = (bid >> 1) & (L_DIM - 1);
    const int j  = ((bid & 1) << 8) + tid;

    const size_t pos   = ((size_t)(b * L_DIM + i) * L_DIM + j);
    const size_t tbase = (size_t)b * C_DIM * SLICE + (size_t)i * L_DIM + j;

    float t[64];
    float s = 0.f, ss = 0.f;
#pragma unroll
    for (int c = 0; c < 64; c++) {
        const float v = g_tri[tbase + (size_t)c * SLICE];
        t[c] = v;
        s += v;
        ss += v * v;
    }
    const float mu   = s * (1.0f / 64.0f);
    const float rstd = rsqrtf(ss * (1.0f / 64.0f) - mu * mu + LN_EPS);
#pragma unroll
    for (int c = 0; c < 64; c++) {
        const float og = g_og[tbase + (size_t)c * SLICE];
        t[c] = ((t[c] - mu) * rstd * lnw[c] + lnb[c]) * og;
    }

    const float4* resid = reinterpret_cast<const float4*>(x + pos * C_DIM);
    float4* o4          = reinterpret_cast<float4*>(out + pos * C_DIM);

#pragma unroll 1
    for (int h = 0; h < 2; h++) {
        unsigned long long acc2[16];
#pragma unroll
        for (int n = 0; n < 16; n++) acc2[n] = 0ull;
#pragma unroll
        for (int c = 0; c < 64; c++) {
            const unsigned long long tc = dup2(t[c]);
            const ulonglong2* wr =
                reinterpret_cast<const ulonglong2*>(Ws + c * 64 + h * 32);
#pragma unroll
            for (int n2 = 0; n2 < 8; n2++) {
                const ulonglong2 w = wr[n2];
                acc2[n2 * 2 + 0] = fma2(tc, w.x, acc2[n2 * 2 + 0]);
                acc2[n2 * 2 + 1] = fma2(tc, w.y, acc2[n2 * 2 + 1]);
            }
        }
#pragma unroll
        for (int n4 = 0; n4 < 8; n4++) {
            const int n = n4 * 4;
            const float2 p0 = unpack2(acc2[n4 * 2 + 0]);
            const float2 p1 = unpack2(acc2[n4 * 2 + 1]);
            const float4 r = resid[h * 8 + n4];
            o4[h * 8 + n4] = make_float4(
                p0.x + bout[h * 32 + n + 0] + r.x,
                p0.y + bout[h * 32 + n + 1] + r.y,
                p1.x + bout[h * 32 + n + 2] + r.z,
                p1.y + bout[h * 32 + n + 3] + r.w);
        }
    }
}

// ---------------------------------------------------------------------------
// Launch
// ---------------------------------------------------------------------------
extern "C" void kernel_launch(void* const* d_in, const int* in_sizes, int n_in,
                              void* d_out, int out_size)
{
    (void)in_sizes; (void)n_in; (void)out_size;
    const float* x    = (const float*)d_in[0];
    const float* am   = (const float*)d_in[1];
    const float* lniw = (const float*)d_in[2];
    const float* lnib = (const float*)d_in[3];
    const float* Wlp  = (const float*)d_in[4];
    const float* blp  = (const float*)d_in[5];
    const float* Wrp  = (const float*)d_in[6];
    const float* brp  = (const float*)d_in[7];
    const float* Wlg  = (const float*)d_in[8];
    const float* blg  = (const float*)d_in[9];
    const float* Wrg  = (const float*)d_in[10];
    const float* brg  = (const float*)d_in[11];
    const float* Wog  = (const float*)d_in[12];
    const float* bog  = (const float*)d_in[13];
    const float* lnow = (const float*)d_in[14];
    const float* lnob = (const float*)d_in[15];
    const float* Wout = (const float*)d_in[16];
    const float* bout = (const float*)d_in[17];
    float* out = (float*)d_out;

    cudaFuncSetAttribute(k_proj, cudaFuncAttributeMaxDynamicSharedMemorySize, PROJ_SMEM);
    cudaFuncSetAttribute(k_tri,  cudaFuncAttributeMaxDynamicSharedMemorySize, TRI_SMEM);

    k_prep<<<1, 256>>>(Wlp, Wlg, Wrp, Wrg, Wog);
    k_proj<<<4096, 256, PROJ_SMEM>>>(x, am, lniw, lnib,
                                     blp, blg, brp, brg, bog);
    k_tri<<<2048, 256, TRI_SMEM>>>();
    k_out<<<2048, 256>>>(x, lnow, lnob, Wout, bout, out);
}